// round 4
// baseline (speedup 1.0000x reference)
#include <cuda_runtime.h>
#include <cuda_fp16.h>

// LSTMPredictor: B=256, T=1024, HID=150, input dim 1, future=0.
// R4: 128 CTAs x 608 threads (19 warps), 2 batches per CTA.
// Lane-pair K-split: threads (2p, 2p+1) co-own gate rows (p, 300+p); lane
// parity selects interleaved 16B chunks of K. Each weight LDS.128 instruction
// moves 512B conflict-free (16 rows x 32B, row stride 336B => 4 phases).
// Partial sums combined via shfl_xor(1). 19 warps hide LDS/HFMA2 latency
// (R3 had only 10). Input staged in smem; sig(f)/sig(o) hoisted off the
// phase-B critical path. fp32 flush of fp16 accumulators every 5 iters.

namespace {

constexpr int HID  = 150;
constexpr int TT   = 1024;
constexpr int NCTA = 128;
constexpr int NTHR = 608;
constexpr int RPW  = 168;   // padded weight/h row length in halves (336 B)
constexpr int NJ   = 10;    // K iterations per lane (each 8 halves, stride 16)
constexpr int GP   = 152;   // fp32 gate/h array pitch (floats)

// Shared memory layout (bytes, 16B-aligned blocks)
constexpr int OFF_WTS  = 0;                       // fp16 [600][168] = 201600
constexpr int OFF_HK   = 201600;                  // fp16 h [2][168] = 672
constexpr int OFF_AS   = 202272;                  // fp32 a [2][152] = 1216
constexpr int OFF_HBUF = 203488;                  // fp32 h [2][152] = 1216
constexpr int OFF_WLIN = 204704;                  // fp32 [152]      = 608
constexpr int OFF_XIN  = 205312;                  // fp32 [2][1024]  = 8192
constexpr int SMEM_BYTES = 213504;

__device__ __forceinline__ float sigf(float x) {
    return __fdividef(1.0f, 1.0f + __expf(-x));
}
__device__ __forceinline__ float tanhfast(float x) {
    return 1.0f - __fdividef(2.0f, __expf(2.0f * x) + 1.0f);
}

__device__ __forceinline__ void fma8(const uint4& w, const uint4& h,
                                     __half2& acc) {
    const __half2* wp = reinterpret_cast<const __half2*>(&w);
    const __half2* hp = reinterpret_cast<const __half2*>(&h);
    acc = __hfma2(wp[0], hp[0], acc);
    acc = __hfma2(wp[1], hp[1], acc);
    acc = __hfma2(wp[2], hp[2], acc);
    acc = __hfma2(wp[3], hp[3], acc);
}

} // namespace

__global__ void __launch_bounds__(NTHR, 1)
lstm_pred_kernel(const float* __restrict__ input,   // [256][1024]
                 const float* __restrict__ W_ih,    // [600][1]
                 const float* __restrict__ W_hh,    // [600][150]
                 const float* __restrict__ b_ih,    // [600]
                 const float* __restrict__ b_hh,    // [600]
                 const float* __restrict__ W_lin,   // [1][150]
                 const float* __restrict__ b_lin,   // [1]
                 float* __restrict__ out)           // [256][1024]
{
    extern __shared__ char smem[];
    __half* wts    = reinterpret_cast<__half*>(smem + OFF_WTS);
    __half* hk     = reinterpret_cast<__half*>(smem + OFF_HK);   // [2][168]
    float*  a_s    = reinterpret_cast<float*>(smem + OFF_AS);    // [2][152]
    float*  hbuf   = reinterpret_cast<float*>(smem + OFF_HBUF);  // [2][152]
    float*  wlin_s = reinterpret_cast<float*>(smem + OFF_WLIN);
    float*  xin    = reinterpret_cast<float*>(smem + OFF_XIN);   // [2][1024]

    const int tid = threadIdx.x;
    const int b0  = blockIdx.x * 2;

    // ---- init (one-time) ----
    // Weights -> fp16 smem, rows padded to RPW halves; pads MUST be zero.
    for (int i = tid; i < 600 * RPW; i += NTHR) {
        const int r = i / RPW, c = i - r * RPW;
        wts[i] = (c < HID) ? __float2half(W_hh[r * HID + c]) : __half(0);
    }
    for (int i = tid; i < HID; i += NTHR) wlin_s[i] = W_lin[i];
    for (int i = tid; i < 2 * RPW; i += NTHR) hk[i] = __half(0);
    // Stage both input rows (coalesced within each row).
    for (int i = tid; i < 2 * TT; i += NTHR)
        xin[i] = input[(b0 + (i >> 10)) * TT + (i & (TT - 1))];

    const int q    = tid;
    const int half = q & 1;
    const int praw = q >> 1;                 // row-pair id (valid < 300)
    const bool act = (q < 600);
    const int p    = act ? praw : 0;
    const int rA   = p;                      // i (p<150) or f (150<=p<300)
    const int rB   = 300 + p;                // g or o

    float wihA = 0.f, wihB = 0.f, biasA = 0.f, biasB = 0.f;
    if (act && half == 0) {
        wihA  = W_ih[rA];
        wihB  = W_ih[rB];
        biasA = b_ih[rA] + b_hh[rA];
        biasB = b_ih[rB] + b_hh[rB];
    }
    float c0 = 0.f, c1 = 0.f;                // cell state (f/o even lanes)
    const float blin = b_lin[0];

    // Per-lane base pointers; lane parity offsets by one 16B chunk, loop
    // strides by 2 chunks => lanes (2p,2p+1) read adjacent 16B of same row.
    const uint4* wAp = reinterpret_cast<const uint4*>(wts + rA * RPW) + half;
    const uint4* wBp = reinterpret_cast<const uint4*>(wts + rB * RPW) + half;
    const uint4* h0p = reinterpret_cast<const uint4*>(hk) + half;
    const uint4* h1p = reinterpret_cast<const uint4*>(hk + RPW) + half;

    __syncthreads();

    for (int t = 0; t < TT; ++t) {
        // ---- phase A: partial dot products over this lane's K chunks ----
        const __half2 z = __float2half2_rn(0.f);
        __half2 aA0 = z, aA1 = z, aB0 = z, aB1 = z;
        float gA0 = 0.f, gA1 = 0.f, gB0 = 0.f, gB1 = 0.f;
#pragma unroll
        for (int j = 0; j < NJ; ++j) {
            const uint4 w4A = wAp[2 * j];     // 512B/warp, 4 phases, no conflict
            const uint4 w4B = wBp[2 * j];
            const uint4 hv0 = h0p[2 * j];     // 2-address broadcast, 1 phase
            const uint4 hv1 = h1p[2 * j];
            fma8(w4A, hv0, aA0);
            fma8(w4A, hv1, aA1);
            fma8(w4B, hv0, aB0);
            fma8(w4B, hv1, aB1);
            if (j == 4 || j == NJ - 1) {      // fp32 flush (40 products max)
                float2 f;
                f = __half22float2(aA0); gA0 += f.x + f.y; aA0 = z;
                f = __half22float2(aA1); gA1 += f.x + f.y; aA1 = z;
                f = __half22float2(aB0); gB0 += f.x + f.y; aB0 = z;
                f = __half22float2(aB1); gB1 += f.x + f.y; aB1 = z;
            }
        }
        // Combine lane-pair partials (full warps execute; q>=600 is dummy).
        gA0 += __shfl_xor_sync(0xffffffffu, gA0, 1);
        gA1 += __shfl_xor_sync(0xffffffffu, gA1, 1);
        gB0 += __shfl_xor_sync(0xffffffffu, gB0, 1);
        gB1 += __shfl_xor_sync(0xffffffffu, gB1, 1);

        float sf0, sf1, so0, so1;
        if (half == 0 && act) {
            const float x0 = xin[t], x1 = xin[TT + t];
            gA0 += fmaf(x0, wihA, biasA);
            gA1 += fmaf(x1, wihA, biasA);
            gB0 += fmaf(x0, wihB, biasB);
            gB1 += fmaf(x1, wihB, biasB);
            if (p < HID) {                    // (i,g): a = sig(i)*tanh(g)
                a_s[p]      = sigf(gA0) * tanhfast(gB0);
                a_s[GP + p] = sigf(gA1) * tanhfast(gB1);
            } else {                          // (f,o): hoist MUFUs off B-path
                sf0 = sigf(gA0); sf1 = sigf(gA1);
                so0 = sigf(gB0); so1 = sigf(gB1);
            }
        }
        __syncthreads();

        // ---- phase B: (f,o) even lanes finish the cell update ----
        if (half == 0 && act && p >= HID) {
            const int j2 = p - HID;
            c0 = fmaf(sf0, c0, a_s[j2]);
            c1 = fmaf(sf1, c1, a_s[GP + j2]);
            const float h0v = so0 * tanhfast(c0);
            const float h1v = so1 * tanhfast(c1);
            hbuf[j2]      = h0v;
            hbuf[GP + j2] = h1v;
            hk[j2]        = __float2half(h0v);
            hk[RPW + j2]  = __float2half(h1v);
        }
        __syncthreads();

        // ---- phase C: output projection (warps 0,1), overlaps next phase A
        // of warps 2..18; hbuf stable until after the next first barrier.
        if (tid < 64) {
            const int bb   = tid >> 5;
            const int lane = tid & 31;
            float s = 0.f;
#pragma unroll
            for (int m = 0; m < 5; ++m) {
                const int j = lane + 32 * m;
                if (j < HID) s = fmaf(hbuf[bb * GP + j], wlin_s[j], s);
            }
#pragma unroll
            for (int off = 16; off; off >>= 1)
                s += __shfl_down_sync(0xffffffffu, s, off);
            if (lane == 0) out[(b0 + bb) * TT + t] = s + blin;
        }
    }
}

extern "C" void kernel_launch(void* const* d_in, const int* in_sizes, int n_in,
                              void* d_out, int out_size) {
    const float* input = (const float*)d_in[0];
    const float* W_ih  = (const float*)d_in[1];
    const float* W_hh  = (const float*)d_in[2];
    const float* b_ih  = (const float*)d_in[3];
    const float* b_hh  = (const float*)d_in[4];
    const float* W_lin = (const float*)d_in[5];
    const float* b_lin = (const float*)d_in[6];
    float* out = (float*)d_out;

    cudaFuncSetAttribute(lstm_pred_kernel,
                         cudaFuncAttributeMaxDynamicSharedMemorySize, SMEM_BYTES);
    lstm_pred_kernel<<<NCTA, NTHR, SMEM_BYTES>>>(input, W_ih, W_hh, b_ih, b_hh,
                                                 W_lin, b_lin, out);
}

// round 5
// speedup vs baseline: 1.2828x; 1.2828x over previous
#include <cuda_runtime.h>
#include <cuda_fp16.h>

// LSTMPredictor: B=256, T=1024, HID=150, input dim 1, future=0.
// R5: 128 CTAs x 320 threads (10 warps), 2 batch rows per CTA.
// WEIGHTS LIVE IN REGISTERS: thread p (<300) owns gate rows (p, 300+p) as
// 2x76 half2 registers (rows padded to 152 halves). The per-step inner loop
// is pure HFMA2 + 38 broadcast LDS.128 of h -> HFMA2-pipe bound
// (~1406 cyc/step floor), no shared-memory crossbar pressure, no bank
// conflicts possible. fp32 flush of fp16 accumulators every <=40 halves.
// (i,g)/(f,o) row pairing fuses the gate split as in R3/R4.

namespace {

constexpr int HID  = 150;
constexpr int TT   = 1024;
constexpr int NCTA = 128;
constexpr int NTHR = 320;
constexpr int NCH  = 19;    // 16B h-chunks per batch (152 halves padded)
constexpr int HP   = 152;   // h pitch in halves
constexpr int GP   = 152;   // fp32 array pitch (floats)

// Shared memory layout (bytes). Small now: ~11.5 KB.
constexpr int OFF_HK   = 0;                     // fp16 h [2][152] = 608
constexpr int OFF_AS   = 608;                   // fp32 a [2][152] = 1216
constexpr int OFF_HBUF = 1824;                  // fp32 h [2][152] = 1216
constexpr int OFF_WLIN = 3040;                  // fp32 [152] = 608
constexpr int OFF_XIN  = 3648;                  // fp32 [2][1024] = 8192
constexpr int SMEM_BYTES = 11840;

__device__ __forceinline__ float sigf(float x) {
    return __fdividef(1.0f, 1.0f + __expf(-x));
}
__device__ __forceinline__ float tanhfast(float x) {
    return 1.0f - __fdividef(2.0f, __expf(2.0f * x) + 1.0f);
}

} // namespace

__global__ void __launch_bounds__(NTHR, 1)
lstm_pred_kernel(const float* __restrict__ input,   // [256][1024]
                 const float* __restrict__ W_ih,    // [600][1]
                 const float* __restrict__ W_hh,    // [600][150]
                 const float* __restrict__ b_ih,    // [600]
                 const float* __restrict__ b_hh,    // [600]
                 const float* __restrict__ W_lin,   // [1][150]
                 const float* __restrict__ b_lin,   // [1]
                 float* __restrict__ out)           // [256][1024]
{
    extern __shared__ char smem[];
    __half* hk     = reinterpret_cast<__half*>(smem + OFF_HK);   // [2][152]
    float*  a_s    = reinterpret_cast<float*>(smem + OFF_AS);    // [2][152]
    float*  hbuf   = reinterpret_cast<float*>(smem + OFF_HBUF);  // [2][152]
    float*  wlin_s = reinterpret_cast<float*>(smem + OFF_WLIN);
    float*  xin    = reinterpret_cast<float*>(smem + OFF_XIN);   // [2][1024]

    const int tid = threadIdx.x;
    const int b0  = blockIdx.x * 2;

    // ---- one-time init ----
    for (int i = tid; i < HID; i += NTHR) wlin_s[i] = W_lin[i];
    for (int i = tid; i < 2 * HP; i += NTHR) hk[i] = __half(0);
    for (int i = tid; i < 2 * TT; i += NTHR)
        xin[i] = input[(b0 + (i >> 10)) * TT + (i & (TT - 1))];

    const int  p   = (tid < 300) ? tid : 0;   // row-pair owner
    const bool act = (tid < 300);
    const int  rA  = p;                       // i (p<150) / f (p>=150)
    const int  rB  = 300 + p;                 // g / o

    // Register-resident fp16 weights: rows rA, rB, padded to 152 halves.
    __half2 wA[NCH * 4], wB[NCH * 4];
    {
        const float* gA = W_hh + rA * HID;
        const float* gB = W_hh + rB * HID;
#pragma unroll
        for (int c = 0; c < NCH * 4; ++c) {
            const int k = 2 * c;
            float a0 = (k     < HID) ? gA[k]     : 0.f;
            float a1 = (k + 1 < HID) ? gA[k + 1] : 0.f;
            float c0f = (k     < HID) ? gB[k]     : 0.f;
            float c1f = (k + 1 < HID) ? gB[k + 1] : 0.f;
            wA[c] = __floats2half2_rn(a0, a1);
            wB[c] = __floats2half2_rn(c0f, c1f);
        }
    }

    float wihA = 0.f, wihB = 0.f, biasA = 0.f, biasB = 0.f;
    if (act) {
        wihA  = W_ih[rA];
        wihB  = W_ih[rB];
        biasA = b_ih[rA] + b_hh[rA];
        biasB = b_ih[rB] + b_hh[rB];
    }
    float c0 = 0.f, c1 = 0.f;                // cell state ((f,o) threads)
    const float blin = b_lin[0];

    const uint4* h0v = reinterpret_cast<const uint4*>(hk);
    const uint4* h1v = reinterpret_cast<const uint4*>(hk + HP);

    __syncthreads();

    for (int t = 0; t < TT; ++t) {
        // ---- phase A: two full gate-row dot products, weights in regs ----
        const __half2 z = __float2half2_rn(0.f);
        __half2 aA0 = z, aA1 = z, aB0 = z, aB1 = z;
        float gA0 = 0.f, gA1 = 0.f, gB0 = 0.f, gB1 = 0.f;
#pragma unroll
        for (int it = 0; it < NCH; ++it) {
            const uint4 u0 = h0v[it];          // broadcast: 1 wavefront
            const uint4 u1 = h1v[it];
            const __half2* h0 = reinterpret_cast<const __half2*>(&u0);
            const __half2* h1 = reinterpret_cast<const __half2*>(&u1);
#pragma unroll
            for (int m = 0; m < 4; ++m) {
                const __half2 a = wA[4 * it + m];
                const __half2 b = wB[4 * it + m];
                aA0 = __hfma2(a, h0[m], aA0);
                aA1 = __hfma2(a, h1[m], aA1);
                aB0 = __hfma2(b, h0[m], aB0);
                aB1 = __hfma2(b, h1[m], aB1);
            }
            if (it == 4 || it == 9 || it == 14 || it == NCH - 1) {
                float2 f;                      // fp32 flush (<=40 halves)
                f = __half22float2(aA0); gA0 += f.x + f.y; aA0 = z;
                f = __half22float2(aA1); gA1 += f.x + f.y; aA1 = z;
                f = __half22float2(aB0); gB0 += f.x + f.y; aB0 = z;
                f = __half22float2(aB1); gB1 += f.x + f.y; aB1 = z;
            }
        }

        float sf0, sf1, so0, so1;
        if (act) {
            const float x0 = xin[t], x1 = xin[TT + t];
            gA0 += fmaf(x0, wihA, biasA);
            gA1 += fmaf(x1, wihA, biasA);
            gB0 += fmaf(x0, wihB, biasB);
            gB1 += fmaf(x1, wihB, biasB);
            if (p < HID) {                     // (i,g): a = sig(i)*tanh(g)
                a_s[p]      = sigf(gA0) * tanhfast(gB0);
                a_s[GP + p] = sigf(gA1) * tanhfast(gB1);
            } else {                           // (f,o): hoist MUFUs here
                sf0 = sigf(gA0); sf1 = sigf(gA1);
                so0 = sigf(gB0); so1 = sigf(gB1);
            }
        }
        __syncthreads();

        // ---- phase B: (f,o) threads finish the cell update ----
        if (act && p >= HID) {
            const int j = p - HID;
            c0 = fmaf(sf0, c0, a_s[j]);
            c1 = fmaf(sf1, c1, a_s[GP + j]);
            const float h0n = so0 * tanhfast(c0);
            const float h1n = so1 * tanhfast(c1);
            hbuf[j]      = h0n;
            hbuf[GP + j] = h1n;
            hk[j]        = __float2half(h0n);
            hk[HP + j]   = __float2half(h1n);
        }
        __syncthreads();

        // ---- phase C: output projection (warps 0,1) overlapping next
        // phase A of warps 2..9; hbuf stable until after next barrier 1.
        if (tid < 64) {
            const int bb   = tid >> 5;
            const int lane = tid & 31;
            float s = 0.f;
#pragma unroll
            for (int m = 0; m < 5; ++m) {
                const int j = lane + 32 * m;
                if (j < HID) s = fmaf(hbuf[bb * GP + j], wlin_s[j], s);
            }
#pragma unroll
            for (int off = 16; off; off >>= 1)
                s += __shfl_down_sync(0xffffffffu, s, off);
            if (lane == 0) out[(b0 + bb) * TT + t] = s + blin;
        }
    }
}

extern "C" void kernel_launch(void* const* d_in, const int* in_sizes, int n_in,
                              void* d_out, int out_size) {
    const float* input = (const float*)d_in[0];
    const float* W_ih  = (const float*)d_in[1];
    const float* W_hh  = (const float*)d_in[2];
    const float* b_ih  = (const float*)d_in[3];
    const float* b_hh  = (const float*)d_in[4];
    const float* W_lin = (const float*)d_in[5];
    const float* b_lin = (const float*)d_in[6];
    float* out = (float*)d_out;

    cudaFuncSetAttribute(lstm_pred_kernel,
                         cudaFuncAttributeMaxDynamicSharedMemorySize, SMEM_BYTES);
    lstm_pred_kernel<<<NCTA, NTHR, SMEM_BYTES>>>(input, W_ih, W_hh, b_ih, b_hh,
                                                 W_lin, b_lin, out);
}

// round 6
// speedup vs baseline: 1.3277x; 1.0350x over previous
#include <cuda_runtime.h>
#include <cuda_fp16.h>

// LSTMPredictor: B=256, T=1024, HID=150, input dim 1, future=0.
// R6: 128 CTAs x 320 threads, 2 batches per CTA, register-resident fp16
// weights (thread pair parity: even lane owns (i_j,g_j), odd owns (f_j,o_j)).
// Fixes vs R5 (which was stall-bound, fma pipe only 44% busy):
//  - explicit distance-1 prefetch of h chunks (LDS latency hidden by 16 HFMA2)
//  - gate exchange via shfl_xor(1) instead of smem a_s (+barrier)
//  - ping-pong h buffers -> ONE __syncthreads per timestep
//  - output projection retimed to out[t-1], overlapped with next dot phase

namespace {

constexpr int HID  = 150;
constexpr int TT   = 1024;
constexpr int NCTA = 128;
constexpr int NTHR = 320;
constexpr int NCH  = 19;    // 16B h-chunks per batch (152 halves padded)
constexpr int HP   = 152;   // h pitch in halves (one batch)
constexpr int GP   = 152;   // fp32 h pitch (floats)

// Shared memory (bytes): double-buffered h (fp16 + fp32), W_lin, staged input
constexpr int OFF_HK   = 0;                    // fp16 [2 buf][2 b][152] = 1216
constexpr int OFF_HBUF = 1216;                 // fp32 [2 buf][2 b][152] = 2432
constexpr int OFF_WLIN = 3648;                 // fp32 [152] = 608
constexpr int OFF_XIN  = 4256;                 // fp32 [2][1024] = 8192
constexpr int SMEM_BYTES = 12448;

__device__ __forceinline__ float sigf(float x) {
    return __fdividef(1.0f, 1.0f + __expf(-x));
}
__device__ __forceinline__ float tanhfast(float x) {
    return 1.0f - __fdividef(2.0f, __expf(2.0f * x) + 1.0f);
}

} // namespace

__global__ void __launch_bounds__(NTHR, 1)
lstm_pred_kernel(const float* __restrict__ input,   // [256][1024]
                 const float* __restrict__ W_ih,    // [600][1]
                 const float* __restrict__ W_hh,    // [600][150]
                 const float* __restrict__ b_ih,    // [600]
                 const float* __restrict__ b_hh,    // [600]
                 const float* __restrict__ W_lin,   // [1][150]
                 const float* __restrict__ b_lin,   // [1]
                 float* __restrict__ out)           // [256][1024]
{
    extern __shared__ char smem[];
    __half* hk     = reinterpret_cast<__half*>(smem + OFF_HK);
    float*  hbuf   = reinterpret_cast<float*>(smem + OFF_HBUF);
    float*  wlin_s = reinterpret_cast<float*>(smem + OFF_WLIN);
    float*  xin    = reinterpret_cast<float*>(smem + OFF_XIN);

    const int tid = threadIdx.x;
    const int b0  = blockIdx.x * 2;

    // ---- one-time init ----
    for (int i = tid; i < HID; i += NTHR) wlin_s[i] = W_lin[i];
    for (int i = tid; i < 2 * 2 * HP; i += NTHR) hk[i] = __half(0); // both bufs
    for (int i = tid; i < 2 * TT; i += NTHR)
        xin[i] = input[(b0 + (i >> 10)) * TT + (i & (TT - 1))];

    const bool act = (tid < 300);
    const int  j   = (act ? tid : 0) >> 1;    // hidden index 0..149
    const int  par = tid & 1;                  // 0: (i,g)  1: (f,o)
    const int  rA  = par * HID + j;            // i_j or f_j
    const int  rB  = 2 * HID + par * HID + j;  // g_j or o_j

    // Register-resident fp16 weights for rows rA, rB (padded to 152 halves).
    __half2 wA[NCH * 4], wB[NCH * 4];
    {
        const float* gA = W_hh + rA * HID;
        const float* gB = W_hh + rB * HID;
#pragma unroll
        for (int c = 0; c < NCH * 4; ++c) {
            const int k = 2 * c;
            const float a0 = (k     < HID) ? gA[k]     : 0.f;
            const float a1 = (k + 1 < HID) ? gA[k + 1] : 0.f;
            const float e0 = (k     < HID) ? gB[k]     : 0.f;
            const float e1 = (k + 1 < HID) ? gB[k + 1] : 0.f;
            wA[c] = __floats2half2_rn(a0, a1);
            wB[c] = __floats2half2_rn(e0, e1);
        }
    }

    float wihA = 0.f, wihB = 0.f, biasA = 0.f, biasB = 0.f;
    if (act) {
        wihA  = W_ih[rA];
        wihB  = W_ih[rB];
        biasA = b_ih[rA] + b_hh[rA];
        biasB = b_ih[rB] + b_hh[rB];
    }
    float c0 = 0.f, c1 = 0.f;               // cell state (odd lanes)
    const float blin = b_lin[0];

    const uint4* hkv = reinterpret_cast<const uint4*>(hk); // 19 u4 per batch

    __syncthreads();

    for (int t = 0; t < TT; ++t) {
        const int cur = t & 1;              // buffer holding h_{t-1}
        const int nxt = cur ^ 1;

        // ---- phase C (retimed): emit out[t-1] from hbuf[cur] = h_{t-1};
        // overlaps the dot phase of warps 2..9. ----
        if (t && tid < 64) {
            const int bb   = tid >> 5;
            const int lane = tid & 31;
            const float* hb = hbuf + cur * 2 * GP + bb * GP;
            float s = 0.f;
#pragma unroll
            for (int m = 0; m < 5; ++m) {
                const int jj = lane + 32 * m;
                if (jj < HID) s = fmaf(hb[jj], wlin_s[jj], s);
            }
#pragma unroll
            for (int off = 16; off; off >>= 1)
                s += __shfl_down_sync(0xffffffffu, s, off);
            if (lane == 0) out[(b0 + bb) * TT + (t - 1)] = s + blin;
        }

        // ---- phase A: dot products vs h_{t-1}, distance-1 prefetch ----
        const uint4* hv = hkv + cur * 38;   // [0..18]=batch0, [19..37]=batch1
        const __half2 z = __float2half2_rn(0.f);
        __half2 aA0 = z, aA1 = z, aB0 = z, aB1 = z;
        float gA0 = 0.f, gA1 = 0.f, gB0 = 0.f, gB1 = 0.f;
        uint4 u0 = hv[0], u1 = hv[19];
#pragma unroll
        for (int it = 0; it < NCH; ++it) {
            uint4 n0, n1;
            if (it < NCH - 1) { n0 = hv[it + 1]; n1 = hv[it + 20]; }
            const __half2* h0 = reinterpret_cast<const __half2*>(&u0);
            const __half2* h1 = reinterpret_cast<const __half2*>(&u1);
#pragma unroll
            for (int m = 0; m < 4; ++m) {
                const __half2 a = wA[4 * it + m];
                const __half2 b = wB[4 * it + m];
                aA0 = __hfma2(a, h0[m], aA0);
                aA1 = __hfma2(a, h1[m], aA1);
                aB0 = __hfma2(b, h0[m], aB0);
                aB1 = __hfma2(b, h1[m], aB1);
            }
            if (it == 9 || it == NCH - 1) {         // fp32 flush
                float2 f;
                f = __half22float2(aA0); gA0 += f.x + f.y; aA0 = z;
                f = __half22float2(aA1); gA1 += f.x + f.y; aA1 = z;
                f = __half22float2(aB0); gB0 += f.x + f.y; aB0 = z;
                f = __half22float2(aB1); gB1 += f.x + f.y; aB1 = z;
            }
            u0 = n0; u1 = n1;
        }

        float a0s = 0.f, a1s = 0.f, sf0, sf1, so0, so1;
        if (act) {
            const float x0 = xin[t], x1 = xin[TT + t];
            gA0 += fmaf(x0, wihA, biasA);
            gA1 += fmaf(x1, wihA, biasA);
            gB0 += fmaf(x0, wihB, biasB);
            gB1 += fmaf(x1, wihB, biasB);
            if (par == 0) {                 // (i,g): a = sig(i)*tanh(g)
                a0s = sigf(gA0) * tanhfast(gB0);
                a1s = sigf(gA1) * tanhfast(gB1);
            } else {                        // (f,o): runs in parallel
                sf0 = sigf(gA0); sf1 = sigf(gA1);
                so0 = sigf(gB0); so1 = sigf(gB1);
            }
        }
        // Exchange a to the odd lane (all 32 lanes of every warp execute).
        const float a0r = __shfl_xor_sync(0xffffffffu, a0s, 1);
        const float a1r = __shfl_xor_sync(0xffffffffu, a1s, 1);

        // ---- phase B: odd lanes finish the cell update into buffer nxt ----
        if (act && par == 1) {
            c0 = fmaf(sf0, c0, a0r);
            c1 = fmaf(sf1, c1, a1r);
            const float h0n = so0 * tanhfast(c0);
            const float h1n = so1 * tanhfast(c1);
            __half* hw = hk + nxt * 2 * HP;
            float*  hb = hbuf + nxt * 2 * GP;
            hb[j]      = h0n;
            hb[GP + j] = h1n;
            hw[j]      = __float2half(h0n);
            hw[HP + j] = __float2half(h1n);
        }
        __syncthreads();   // h_t visible for step t+1 readers
    }

    // ---- epilogue: out[TT-1] from hbuf[TT & 1] ----
    if (tid < 64) {
        const int bb   = tid >> 5;
        const int lane = tid & 31;
        const float* hb = hbuf + (TT & 1) * 2 * GP + bb * GP;
        float s = 0.f;
#pragma unroll
        for (int m = 0; m < 5; ++m) {
            const int jj = lane + 32 * m;
            if (jj < HID) s = fmaf(hb[jj], wlin_s[jj], s);
        }
#pragma unroll
        for (int off = 16; off; off >>= 1)
            s += __shfl_down_sync(0xffffffffu, s, off);
        if (lane == 0) out[(b0 + bb) * TT + (TT - 1)] = s + blin;
    }
}

extern "C" void kernel_launch(void* const* d_in, const int* in_sizes, int n_in,
                              void* d_out, int out_size) {
    const float* input = (const float*)d_in[0];
    const float* W_ih  = (const float*)d_in[1];
    const float* W_hh  = (const float*)d_in[2];
    const float* b_ih  = (const float*)d_in[3];
    const float* b_hh  = (const float*)d_in[4];
    const float* W_lin = (const float*)d_in[5];
    const float* b_lin = (const float*)d_in[6];
    float* out = (float*)d_out;

    cudaFuncSetAttribute(lstm_pred_kernel,
                         cudaFuncAttributeMaxDynamicSharedMemorySize, SMEM_BYTES);
    lstm_pred_kernel<<<NCTA, NTHR, SMEM_BYTES>>>(input, W_ih, W_hh, b_ih, b_hh,
                                                 W_lin, b_lin, out);
}